// round 2
// baseline (speedup 1.0000x reference)
#include <cuda_runtime.h>
#include <cstdint>

#define MAX_NODES 50000
#define MAX_EDGES 800000

// Scratch (allocations are forbidden; use __device__ globals)
__device__ float g_agg[MAX_NODES * 64];
__device__ float g_deg[MAX_NODES];

// ---------------------------------------------------------------------------
// Kernel 0: zero the aggregation scratch
// ---------------------------------------------------------------------------
__global__ void zero_kernel(int n_nodes) {
    int i = blockIdx.x * blockDim.x + threadIdx.x;
    int stride = gridDim.x * blockDim.x;
    int tot = n_nodes * 64;
    for (int k = i; k < tot; k += stride) g_agg[k] = 0.0f;
    for (int k = i; k < n_nodes; k += stride) g_deg[k] = 0.0f;
}

// ---------------------------------------------------------------------------
// Kernel 1: edge MLP + atomic aggregation
//   x = [feats[r] | feats[c] | edge_attr]  (192)
//   e = relu(x @ W1e + b1e) @ W2e + b2e    (64)
//   agg[c] += e ; deg[c] += 1
// ---------------------------------------------------------------------------
#define EDGE_SMEM_FLOATS 24704

__global__ void __launch_bounds__(256, 2) edge_kernel(
    const float* __restrict__ feats,
    const int* __restrict__ edge_index,   // int32 pairs [n_edges][2]
    const float* __restrict__ edge_attr,
    const float* __restrict__ W1e, const float* __restrict__ b1e,
    const float* __restrict__ W2e, const float* __restrict__ b2e,
    float* __restrict__ e_out,
    int n_edges)
{
    extern __shared__ float smem[];
    float2* sW1 = (float2*)smem;                 // [192*32]
    float2* sW2 = (float2*)(smem + 12288);       // [64*32]
    float2* sb1 = (float2*)(smem + 16384);       // [32]
    float2* sb2 = (float2*)(smem + 16448);       // [32]
    float*  xbuf = smem + 16512;                 // 8*4*192
    float*  hbuf = smem + 22656;                 // 8*4*64

    int tid = threadIdx.x;
    for (int i = tid; i < 192 * 32; i += 256) {
        int k = i >> 5, l = i & 31;
        sW1[i] = make_float2(W1e[k * 64 + l], W1e[k * 64 + l + 32]);
    }
    for (int i = tid; i < 64 * 32; i += 256) {
        int k = i >> 5, l = i & 31;
        sW2[i] = make_float2(W2e[k * 64 + l], W2e[k * 64 + l + 32]);
    }
    if (tid < 32) {
        sb1[tid] = make_float2(b1e[tid], b1e[tid + 32]);
        sb2[tid] = make_float2(b2e[tid], b2e[tid + 32]);
    }
    __syncthreads();

    int warp = tid >> 5, lane = tid & 31;
    float* xw = xbuf + warp * 4 * 192;
    float* hw = hbuf + warp * 4 * 64;

    int nGroups = (n_edges + 3) >> 2;
    int gwarp = blockIdx.x * 8 + warp;
    int wstride = gridDim.x * 8;

    for (int g = gwarp; g < nGroups; g += wstride) {
        int ebase = g * 4;
        int nE = min(4, n_edges - ebase);

        // lanes 0..3 fetch (r, c) for their edge
        int r = 0, c = 0;
        if (lane < 4) {
            int eid = ebase + min(lane, nE - 1);
            int2 rc = ((const int2*)edge_index)[eid];
            r = rc.x; c = rc.y;
        }

        // Gather x: 4 edges * 48 float4 = 192 float4
        for (int i = lane; i < 192; i += 32) {
            int j = i / 48;
            int part = (i % 48) >> 4;
            int q = i & 15;
            int rj = __shfl_sync(0xffffffffu, r, j);
            int cj = __shfl_sync(0xffffffffu, c, j);
            int eid = ebase + min(j, nE - 1);
            const float4* src;
            if (part == 0)      src = (const float4*)(feats + (size_t)rj * 64);
            else if (part == 1) src = (const float4*)(feats + (size_t)cj * 64);
            else                src = (const float4*)(edge_attr + (size_t)eid * 64);
            ((float4*)(xw + j * 192 + part * 64))[q] = src[q];
        }
        __syncwarp();

        // GEMM1: hidden[j][lane], hidden[j][lane+32]
        float2 bb = sb1[lane];
        float2 acc0 = bb, acc1 = bb, acc2 = bb, acc3 = bb;
        #pragma unroll 4
        for (int k = 0; k < 192; k += 2) {
            float2 w0 = sW1[k * 32 + lane];
            float2 w1 = sW1[(k + 1) * 32 + lane];
            float2 x0 = *(const float2*)(xw + 0 * 192 + k);
            float2 x1 = *(const float2*)(xw + 1 * 192 + k);
            float2 x2 = *(const float2*)(xw + 2 * 192 + k);
            float2 x3 = *(const float2*)(xw + 3 * 192 + k);
            acc0.x = fmaf(x0.x, w0.x, fmaf(x0.y, w1.x, acc0.x));
            acc0.y = fmaf(x0.x, w0.y, fmaf(x0.y, w1.y, acc0.y));
            acc1.x = fmaf(x1.x, w0.x, fmaf(x1.y, w1.x, acc1.x));
            acc1.y = fmaf(x1.x, w0.y, fmaf(x1.y, w1.y, acc1.y));
            acc2.x = fmaf(x2.x, w0.x, fmaf(x2.y, w1.x, acc2.x));
            acc2.y = fmaf(x2.x, w0.y, fmaf(x2.y, w1.y, acc2.y));
            acc3.x = fmaf(x3.x, w0.x, fmaf(x3.y, w1.x, acc3.x));
            acc3.y = fmaf(x3.x, w0.y, fmaf(x3.y, w1.y, acc3.y));
        }
        hw[0 * 64 + lane]      = fmaxf(acc0.x, 0.0f);
        hw[0 * 64 + lane + 32] = fmaxf(acc0.y, 0.0f);
        hw[1 * 64 + lane]      = fmaxf(acc1.x, 0.0f);
        hw[1 * 64 + lane + 32] = fmaxf(acc1.y, 0.0f);
        hw[2 * 64 + lane]      = fmaxf(acc2.x, 0.0f);
        hw[2 * 64 + lane + 32] = fmaxf(acc2.y, 0.0f);
        hw[3 * 64 + lane]      = fmaxf(acc3.x, 0.0f);
        hw[3 * 64 + lane + 32] = fmaxf(acc3.y, 0.0f);
        __syncwarp();

        // GEMM2: e[j][lane], e[j][lane+32]
        float2 b2v = sb2[lane];
        float2 o0 = b2v, o1 = b2v, o2 = b2v, o3 = b2v;
        #pragma unroll 4
        for (int k = 0; k < 64; k += 2) {
            float2 w0 = sW2[k * 32 + lane];
            float2 w1 = sW2[(k + 1) * 32 + lane];
            float2 h0 = *(const float2*)(hw + 0 * 64 + k);
            float2 h1 = *(const float2*)(hw + 1 * 64 + k);
            float2 h2 = *(const float2*)(hw + 2 * 64 + k);
            float2 h3 = *(const float2*)(hw + 3 * 64 + k);
            o0.x = fmaf(h0.x, w0.x, fmaf(h0.y, w1.x, o0.x));
            o0.y = fmaf(h0.x, w0.y, fmaf(h0.y, w1.y, o0.y));
            o1.x = fmaf(h1.x, w0.x, fmaf(h1.y, w1.x, o1.x));
            o1.y = fmaf(h1.x, w0.y, fmaf(h1.y, w1.y, o1.y));
            o2.x = fmaf(h2.x, w0.x, fmaf(h2.y, w1.x, o2.x));
            o2.y = fmaf(h2.x, w0.y, fmaf(h2.y, w1.y, o2.y));
            o3.x = fmaf(h3.x, w0.x, fmaf(h3.y, w1.x, o3.x));
            o3.y = fmaf(h3.x, w0.y, fmaf(h3.y, w1.y, o3.y));
        }

        float2 outs[4] = {o0, o1, o2, o3};
        #pragma unroll
        for (int j = 0; j < 4; j++) {
            if (j >= nE) break;
            int eid = ebase + j;
            int cj = __shfl_sync(0xffffffffu, c, j);
            size_t base = (size_t)eid * 64;
            e_out[base + lane]      = outs[j].x;
            e_out[base + lane + 32] = outs[j].y;
            atomicAdd(&g_agg[(size_t)cj * 64 + lane],      outs[j].x);
            atomicAdd(&g_agg[(size_t)cj * 64 + lane + 32], outs[j].y);
            if (lane == 0) atomicAdd(&g_deg[cj], 1.0f);
        }
    }
}

// ---------------------------------------------------------------------------
// Kernel 2: node MLP
//   h = [feats | agg/max(deg,1)] (128)
//   feats_out = relu(h @ W1n + b1n) @ W2n + b2n
// ---------------------------------------------------------------------------
#define NODE_SMEM_FLOATS 18560

__global__ void __launch_bounds__(256, 2) node_kernel(
    const float* __restrict__ feats,
    const float* __restrict__ W1n, const float* __restrict__ b1n,
    const float* __restrict__ W2n, const float* __restrict__ b2n,
    float* __restrict__ feats_out,
    int n_nodes)
{
    extern __shared__ float smem[];
    float2* sW1 = (float2*)smem;                 // [128*32]
    float2* sW2 = (float2*)(smem + 8192);        // [64*32]
    float2* sb1 = (float2*)(smem + 12288);       // [32]
    float2* sb2 = (float2*)(smem + 12352);       // [32]
    float*  xbuf = smem + 12416;
    float*  hbuf = smem + 16512;

    int tid = threadIdx.x;
    for (int i = tid; i < 128 * 32; i += 256) {
        int k = i >> 5, l = i & 31;
        sW1[i] = make_float2(W1n[k * 64 + l], W1n[k * 64 + l + 32]);
    }
    for (int i = tid; i < 64 * 32; i += 256) {
        int k = i >> 5, l = i & 31;
        sW2[i] = make_float2(W2n[k * 64 + l], W2n[k * 64 + l + 32]);
    }
    if (tid < 32) {
        sb1[tid] = make_float2(b1n[tid], b1n[tid + 32]);
        sb2[tid] = make_float2(b2n[tid], b2n[tid + 32]);
    }
    __syncthreads();

    int warp = tid >> 5, lane = tid & 31;
    float* xw = xbuf + warp * 4 * 128;
    float* hw = hbuf + warp * 4 * 64;

    int nGroups = (n_nodes + 3) >> 2;
    int gwarp = blockIdx.x * 8 + warp;
    int wstride = gridDim.x * 8;

    for (int g = gwarp; g < nGroups; g += wstride) {
        int nbase = g * 4;
        int nN = min(4, n_nodes - nbase);

        float invd = 1.0f;
        if (lane < 4) {
            int nid = nbase + min(lane, nN - 1);
            invd = 1.0f / fmaxf(g_deg[nid], 1.0f);
        }

        // Gather h: 4 nodes * 32 float4 = 128 float4
        for (int i = lane; i < 128; i += 32) {
            int j = i >> 5;
            int part = (i >> 4) & 1;
            int q = i & 15;
            int nid = nbase + min(j, nN - 1);
            float s = __shfl_sync(0xffffffffu, invd, j);
            float4 v;
            if (part == 0) {
                v = ((const float4*)(feats + (size_t)nid * 64))[q];
            } else {
                v = ((const float4*)(g_agg + (size_t)nid * 64))[q];
                v.x *= s; v.y *= s; v.z *= s; v.w *= s;
            }
            ((float4*)(xw + j * 128 + part * 64))[q] = v;
        }
        __syncwarp();

        float2 bb = sb1[lane];
        float2 acc0 = bb, acc1 = bb, acc2 = bb, acc3 = bb;
        #pragma unroll 4
        for (int k = 0; k < 128; k += 2) {
            float2 w0 = sW1[k * 32 + lane];
            float2 w1 = sW1[(k + 1) * 32 + lane];
            float2 x0 = *(const float2*)(xw + 0 * 128 + k);
            float2 x1 = *(const float2*)(xw + 1 * 128 + k);
            float2 x2 = *(const float2*)(xw + 2 * 128 + k);
            float2 x3 = *(const float2*)(xw + 3 * 128 + k);
            acc0.x = fmaf(x0.x, w0.x, fmaf(x0.y, w1.x, acc0.x));
            acc0.y = fmaf(x0.x, w0.y, fmaf(x0.y, w1.y, acc0.y));
            acc1.x = fmaf(x1.x, w0.x, fmaf(x1.y, w1.x, acc1.x));
            acc1.y = fmaf(x1.x, w0.y, fmaf(x1.y, w1.y, acc1.y));
            acc2.x = fmaf(x2.x, w0.x, fmaf(x2.y, w1.x, acc2.x));
            acc2.y = fmaf(x2.x, w0.y, fmaf(x2.y, w1.y, acc2.y));
            acc3.x = fmaf(x3.x, w0.x, fmaf(x3.y, w1.x, acc3.x));
            acc3.y = fmaf(x3.x, w0.y, fmaf(x3.y, w1.y, acc3.y));
        }
        hw[0 * 64 + lane]      = fmaxf(acc0.x, 0.0f);
        hw[0 * 64 + lane + 32] = fmaxf(acc0.y, 0.0f);
        hw[1 * 64 + lane]      = fmaxf(acc1.x, 0.0f);
        hw[1 * 64 + lane + 32] = fmaxf(acc1.y, 0.0f);
        hw[2 * 64 + lane]      = fmaxf(acc2.x, 0.0f);
        hw[2 * 64 + lane + 32] = fmaxf(acc2.y, 0.0f);
        hw[3 * 64 + lane]      = fmaxf(acc3.x, 0.0f);
        hw[3 * 64 + lane + 32] = fmaxf(acc3.y, 0.0f);
        __syncwarp();

        float2 b2v = sb2[lane];
        float2 o0 = b2v, o1 = b2v, o2 = b2v, o3 = b2v;
        #pragma unroll 4
        for (int k = 0; k < 64; k += 2) {
            float2 w0 = sW2[k * 32 + lane];
            float2 w1 = sW2[(k + 1) * 32 + lane];
            float2 h0 = *(const float2*)(hw + 0 * 64 + k);
            float2 h1 = *(const float2*)(hw + 1 * 64 + k);
            float2 h2 = *(const float2*)(hw + 2 * 64 + k);
            float2 h3 = *(const float2*)(hw + 3 * 64 + k);
            o0.x = fmaf(h0.x, w0.x, fmaf(h0.y, w1.x, o0.x));
            o0.y = fmaf(h0.x, w0.y, fmaf(h0.y, w1.y, o0.y));
            o1.x = fmaf(h1.x, w0.x, fmaf(h1.y, w1.x, o1.x));
            o1.y = fmaf(h1.x, w0.y, fmaf(h1.y, w1.y, o1.y));
            o2.x = fmaf(h2.x, w0.x, fmaf(h2.y, w1.x, o2.x));
            o2.y = fmaf(h2.x, w0.y, fmaf(h2.y, w1.y, o2.y));
            o3.x = fmaf(h3.x, w0.x, fmaf(h3.y, w1.x, o3.x));
            o3.y = fmaf(h3.x, w0.y, fmaf(h3.y, w1.y, o3.y));
        }

        float2 outs[4] = {o0, o1, o2, o3};
        #pragma unroll
        for (int j = 0; j < 4; j++) {
            if (j >= nN) break;
            size_t base = (size_t)(nbase + j) * 64;
            feats_out[base + lane]      = outs[j].x;
            feats_out[base + lane + 32] = outs[j].y;
        }
    }
}

// ---------------------------------------------------------------------------
extern "C" void kernel_launch(void* const* d_in, const int* in_sizes, int n_in,
                              void* d_out, int out_size) {
    const float* feats      = (const float*)d_in[0];
    const int*   edge_index = (const int*)d_in[1];
    const float* edge_attr  = (const float*)d_in[2];
    const float* W1e        = (const float*)d_in[3];
    const float* b1e        = (const float*)d_in[4];
    const float* W2e        = (const float*)d_in[5];
    const float* b2e        = (const float*)d_in[6];
    const float* W1n        = (const float*)d_in[7];
    const float* b1n        = (const float*)d_in[8];
    const float* W2n        = (const float*)d_in[9];
    const float* b2n        = (const float*)d_in[10];

    int n_nodes = in_sizes[0] / 64;
    int n_edges = in_sizes[2] / 64;

    float* out       = (float*)d_out;
    float* feats_out = out;                            // [n_nodes, 64]
    float* e_out     = out + (size_t)n_nodes * 64;     // [n_edges, 64]

    size_t edge_smem = EDGE_SMEM_FLOATS * sizeof(float);
    size_t node_smem = NODE_SMEM_FLOATS * sizeof(float);
    cudaFuncSetAttribute(edge_kernel, cudaFuncAttributeMaxDynamicSharedMemorySize, (int)edge_smem);
    cudaFuncSetAttribute(node_kernel, cudaFuncAttributeMaxDynamicSharedMemorySize, (int)node_smem);

    zero_kernel<<<1024, 256>>>(n_nodes);
    edge_kernel<<<296, 256, edge_smem>>>(feats, edge_index, edge_attr,
                                         W1e, b1e, W2e, b2e, e_out, n_edges);
    node_kernel<<<296, 256, node_smem>>>(feats, W1n, b1n, W2n, b2n,
                                         feats_out, n_nodes);
}